// round 4
// baseline (speedup 1.0000x reference)
#include <cuda_runtime.h>

#define NU 200000
#define NR 200000
#define HDIM 64
#define EDGES 4000000
#define SCAN_B 1024
#define M2 (2 * NU)
#define NSCANB ((M2 + SCAN_B - 1) / SCAN_B)   // 391

typedef unsigned long long ull;

// ---------------- static device scratch ----------------
__device__ float g_xr0[(size_t)NR * HDIM];
__device__ float g_xr1[(size_t)NR * HDIM];
__device__ float g_xu1[(size_t)NU * HDIM];
__device__ float g_xu2[(size_t)NU * HDIM];
__device__ float g_mean_r[(size_t)NR * HDIM];
__device__ float g_mean_u[(size_t)NU * HDIM];
__device__ float g_mean_r2[(size_t)NR * HDIM];
__device__ float g_mean_u2[(size_t)NU * HDIM];
__device__ int   g_nbr_r[EDGES];
__device__ int   g_nbr_u[EDGES];
__device__ int   g_off_u[NU + 1];
__device__ int   g_off_r[NR + 1];
__device__ int   g_deg[M2];
__device__ int   g_cur[M2];
__device__ volatile ull g_scan_state[NSCANB];

// ---------------- CSR: count (also resets scan state) ----------------
__global__ void k_count(const int* __restrict__ ei, int* __restrict__ deg, int e) {
    if (blockIdx.x == 0 && threadIdx.x < NSCANB)
        *(ull*)&g_scan_state[threadIdx.x] = 0ull;
    int i = blockIdx.x * blockDim.x + threadIdx.x;
    if (i < e) {
        atomicAdd(&deg[ei[i]], 1);           // user src
        atomicAdd(&deg[NU + ei[e + i]], 1);  // recipe dst
    }
}

// ---------------- CSR: single-kernel scan (decoupled lookback) ----------------
__global__ void __launch_bounds__(SCAN_B) k_scan_lb(
    const int* __restrict__ deg, int* __restrict__ off_u, int* __restrict__ off_r,
    int n, int etot) {
    __shared__ int sh[SCAN_B];
    __shared__ int s_prefix;
    int b = blockIdx.x;
    int i = b * SCAN_B + threadIdx.x;
    int v = (i < n) ? deg[i] : 0;
    sh[threadIdx.x] = v;
    __syncthreads();
    for (int s = 1; s < SCAN_B; s <<= 1) {
        int t = (threadIdx.x >= s) ? sh[threadIdx.x - s] : 0;
        __syncthreads();
        sh[threadIdx.x] += t;
        __syncthreads();
    }
    int incl_local = sh[threadIdx.x];
    int total = sh[SCAN_B - 1];

    if (threadIdx.x == 0) {
        if (b == 0) {
            atomicExch((ull*)&g_scan_state[0], ((ull)2 << 32) | (unsigned)total);
            s_prefix = 0;
        } else {
            atomicExch((ull*)&g_scan_state[b], ((ull)1 << 32) | (unsigned)total);
            int prefix = 0;
            for (int p = b - 1; p >= 0;) {
                ull st;
                do { st = g_scan_state[p]; } while ((st >> 32) == 0);
                prefix += (int)(unsigned)st;
                if ((st >> 32) == 2) break;
                p--;
            }
            atomicExch((ull*)&g_scan_state[b], ((ull)2 << 32) | (unsigned)(prefix + total));
            s_prefix = prefix;
        }
    }
    __syncthreads();

    int excl = s_prefix + incl_local - v;
    if (i < n) {
        if (i < NU) off_u[i] = excl;
        else        off_r[i - NU] = excl - etot;
        if (i == NU) off_u[NU] = excl;           // == etot
        if (i == n - 1) off_r[NR] = excl + v - etot;
    }
}

__global__ void k_fill(const int* __restrict__ ei,
                       const int* __restrict__ off_u, const int* __restrict__ off_r,
                       int* __restrict__ cur,
                       int* __restrict__ nbr_u, int* __restrict__ nbr_r, int e) {
    int i = blockIdx.x * blockDim.x + threadIdx.x;
    if (i < e) {
        int s = ei[i], d = ei[e + i];
        int pu = atomicAdd(&cur[s], 1);
        nbr_u[off_u[s] + pu] = d;
        int pr = atomicAdd(&cur[NU + d], 1);
        nbr_r[off_r[d] + pr] = s;
    }
}

// ---------------- mean aggregation: warp per node, float4 x 2 neighbors/step ----------------
__global__ void __launch_bounds__(256) k_aggregate(
    const int* __restrict__ off, const int* __restrict__ nbr,
    const float* __restrict__ xsrc, float* __restrict__ mean, int n) {
    int w = (blockIdx.x * blockDim.x + threadIdx.x) >> 5;
    int lane = threadIdx.x & 31;
    if (w >= n) return;
    int beg = off[w], end = off[w + 1];
    int half = lane >> 4;      // 0: neighbor t, 1: neighbor t+1
    int hl = lane & 15;        // 16 lanes x float4 = one 64-float row
    const float4* X = (const float4*)xsrc;
    float ax = 0.f, ay = 0.f, az = 0.f, aw = 0.f;

    for (int j = beg; j < end; j += 32) {
        int cnt = end - j; if (cnt > 32) cnt = 32;
        int idx = (lane < cnt) ? nbr[j + lane] : 0;
        int t = 0;
        for (; t + 16 <= cnt; t += 16) {
#pragma unroll
            for (int s = 0; s < 8; s++) {
                int r = __shfl_sync(0xffffffffu, idx, t + 2 * s + half);
                float4 v = X[(size_t)r * 16 + hl];
                ax += v.x; ay += v.y; az += v.z; aw += v.w;
            }
        }
        for (; t < cnt; t += 2) {
            int u = t + half;
            int r = __shfl_sync(0xffffffffu, idx, (u < cnt) ? u : t);
            if (u < cnt) {
                float4 v = X[(size_t)r * 16 + hl];
                ax += v.x; ay += v.y; az += v.z; aw += v.w;
            }
        }
    }
    // fold the two neighbor-halves (same columns)
    ax += __shfl_down_sync(0xffffffffu, ax, 16);
    ay += __shfl_down_sync(0xffffffffu, ay, 16);
    az += __shfl_down_sync(0xffffffffu, az, 16);
    aw += __shfl_down_sync(0xffffffffu, aw, 16);
    if (lane < 16) {
        float inv = 1.0f / fmaxf((float)(end - beg), 1.0f);
        ((float4*)mean)[(size_t)w * 16 + hl] =
            make_float4(ax * inv, ay * inv, az * inv, aw * inv);
    }
}

// ---------------- transform: out = A0@W0 + bias + A1@W1 (+relu), FFMA2 ----------------
#define FMA2(d, a, b) asm("fma.rn.f32x2 %0, %1, %2, %0;" : "+l"(d) : "l"(a), "l"(b))

__global__ void __launch_bounds__(256) k_transform(
    const float* __restrict__ A0, const float* __restrict__ A1,
    const float* __restrict__ W0, const float* __restrict__ W1,
    const float* __restrict__ bias, float* __restrict__ out, int n, int relu) {
    extern __shared__ float smem[];
    float* sA = smem;              // 128 x 65 (padded)
    float* sW = smem + 128 * 65;   // 64 x 64
    const int t  = threadIdx.x;
    const int tx = t & 7;          // col group: cols 8*tx .. 8*tx+7
    const int ty = t >> 3;         // row group: rows 4*ty .. 4*ty+3
    const int rbase = blockIdx.x * 128;

    ull acc[4][4];
#pragma unroll
    for (int i = 0; i < 4; i++)
#pragma unroll
        for (int j = 0; j < 4; j++) acc[i][j] = 0ull;

#pragma unroll
    for (int ph = 0; ph < 2; ph++) {
        const float* A = ph ? A1 : A0;
        const float* W = ph ? W1 : W0;
        __syncthreads();
#pragma unroll
        for (int u = 0; u < 4; u++)
            ((float4*)sW)[t + u * 256] = ((const float4*)W)[t + u * 256];
#pragma unroll
        for (int u = 0; u < 8; u++) {
            int idx4 = t + u * 256;
            int r = idx4 >> 4, kc = idx4 & 15;
            int gr = rbase + r; if (gr >= n) gr = rbase;
            float4 v = ((const float4*)(A + (size_t)gr * 64))[kc];
            float* dp = sA + r * 65 + kc * 4;
            dp[0] = v.x; dp[1] = v.y; dp[2] = v.z; dp[3] = v.w;
        }
        __syncthreads();

        const ull* sW2 = (const ull*)sW;
#pragma unroll 8
        for (int k = 0; k < 64; k++) {
            ull w2[4];
#pragma unroll
            for (int j = 0; j < 4; j++) w2[j] = sW2[k * 32 + tx * 4 + j];
            ull a2[4];
#pragma unroll
            for (int i = 0; i < 4; i++) {
                unsigned av = __float_as_uint(sA[(ty * 4 + i) * 65 + k]);
                asm("mov.b64 %0, {%1, %1};" : "=l"(a2[i]) : "r"(av));
            }
#pragma unroll
            for (int i = 0; i < 4; i++)
#pragma unroll
                for (int j = 0; j < 4; j++)
                    FMA2(acc[i][j], a2[i], w2[j]);
        }
    }

    float4 b0 = ((const float4*)bias)[tx * 2];
    float4 b1 = ((const float4*)bias)[tx * 2 + 1];
    float bc[8] = {b0.x, b0.y, b0.z, b0.w, b1.x, b1.y, b1.z, b1.w};
#pragma unroll
    for (int i = 0; i < 4; i++) {
        int row = rbase + ty * 4 + i;
        if (row >= n) continue;
        float c[8];
#pragma unroll
        for (int j = 0; j < 4; j++) {
            unsigned lo, hi;
            asm("mov.b64 {%0, %1}, %2;" : "=r"(lo), "=r"(hi) : "l"(acc[i][j]));
            c[2 * j]     = __uint_as_float(lo) + bc[2 * j];
            c[2 * j + 1] = __uint_as_float(hi) + bc[2 * j + 1];
        }
        if (relu) {
#pragma unroll
            for (int j = 0; j < 8; j++) c[j] = fmaxf(c[j], 0.f);
        }
        float4* op = (float4*)(out + (size_t)row * 64 + tx * 8);
        op[0] = make_float4(c[0], c[1], c[2], c[3]);
        op[1] = make_float4(c[4], c[5], c[6], c[7]);
    }
}

// ---------------- x_recipe init ----------------
__global__ void __launch_bounds__(256) k_init_recipe(
    const float* __restrict__ rx, const float* __restrict__ lw,
    const float* __restrict__ lb, const float* __restrict__ remb,
    float* __restrict__ xout, int n) {
    __shared__ float slw[640];
    __shared__ float slb[64];
    int t = threadIdx.x;
    for (int i = t; i < 640; i += 256) slw[i] = lw[i];
    if (t < 64) slb[t] = lb[t];
    __syncthreads();
    int idx4 = blockIdx.x * 256 + t;
    if (idx4 >= n * 16) return;
    int r = idx4 >> 4;
    int h0 = (idx4 & 15) * 4;
    float4 acc = make_float4(slb[h0], slb[h0 + 1], slb[h0 + 2], slb[h0 + 3]);
    const float* xr = rx + r * 10;
#pragma unroll
    for (int k = 0; k < 10; k++) {
        float xv = xr[k];
        const float* wr = slw + k * 64 + h0;
        acc.x = fmaf(xv, wr[0], acc.x);
        acc.y = fmaf(xv, wr[1], acc.y);
        acc.z = fmaf(xv, wr[2], acc.z);
        acc.w = fmaf(xv, wr[3], acc.w);
    }
    float4 e = ((const float4*)remb)[idx4];
    acc.x += e.x; acc.y += e.y; acc.z += e.z; acc.w += e.w;
    ((float4*)xout)[idx4] = acc;
}

// ---------------- classifier: half-warp per label edge ----------------
__global__ void __launch_bounds__(256) k_classify(
    const int* __restrict__ eli, const float* __restrict__ xu,
    const float* __restrict__ xr, float* __restrict__ out, int nl) {
    int hw = (blockIdx.x * blockDim.x + threadIdx.x) >> 4;
    int hl = threadIdx.x & 15;
    if (hw >= nl) return;
    int a = eli[hw], b = eli[nl + hw];
    float4 va = ((const float4*)xu)[(size_t)a * 16 + hl];
    float4 vb = ((const float4*)xr)[(size_t)b * 16 + hl];
    float s = va.x * vb.x + va.y * vb.y + va.z * vb.z + va.w * vb.w;
    s += __shfl_down_sync(0xffffffffu, s, 8, 16);
    s += __shfl_down_sync(0xffffffffu, s, 4, 16);
    s += __shfl_down_sync(0xffffffffu, s, 2, 16);
    s += __shfl_down_sync(0xffffffffu, s, 1, 16);
    if (hl == 0) out[hw] = s;
}

// ---------------- launch: single stream; agg_r0 is the 4th kernel (ncu target) ----------------
extern "C" void kernel_launch(void* const* d_in, const int* in_sizes, int n_in,
                              void* d_out, int out_size) {
    const float* recipe_x   = (const float*)d_in[2];
    const int*   edge_index = (const int*)d_in[3];
    const int*   eli        = (const int*)d_in[4];
    const float* user_emb   = (const float*)d_in[5];
    const float* recipe_emb = (const float*)d_in[6];
    const float* lin_w      = (const float*)d_in[7];
    const float* lin_b      = (const float*)d_in[8];
    const float* Wl         = (const float*)d_in[9];
    const float* bl         = (const float*)d_in[10];
    const float* Wr         = (const float*)d_in[11];
    float* out = (float*)d_out;
    int E_ = in_sizes[3] / 2;
    int L_ = in_sizes[4] / 2;

    float *xr0, *xr1, *xu1, *xu2, *mean_r, *mean_u, *mean_r2, *mean_u2;
    int *nbr_r, *nbr_u, *off_u, *off_r, *deg, *cur;
    cudaGetSymbolAddress((void**)&xr0,     g_xr0);
    cudaGetSymbolAddress((void**)&xr1,     g_xr1);
    cudaGetSymbolAddress((void**)&xu1,     g_xu1);
    cudaGetSymbolAddress((void**)&xu2,     g_xu2);
    cudaGetSymbolAddress((void**)&mean_r,  g_mean_r);
    cudaGetSymbolAddress((void**)&mean_u,  g_mean_u);
    cudaGetSymbolAddress((void**)&mean_r2, g_mean_r2);
    cudaGetSymbolAddress((void**)&mean_u2, g_mean_u2);
    cudaGetSymbolAddress((void**)&nbr_r,   g_nbr_r);
    cudaGetSymbolAddress((void**)&nbr_u,   g_nbr_u);
    cudaGetSymbolAddress((void**)&off_u,   g_off_u);
    cudaGetSymbolAddress((void**)&off_r,   g_off_r);
    cudaGetSymbolAddress((void**)&deg,     g_deg);
    cudaGetSymbolAddress((void**)&cur,     g_cur);

    const int TR_SMEM = (128 * 65 + 64 * 64) * 4;  // 49664 B
    cudaFuncSetAttribute(k_transform, cudaFuncAttributeMaxDynamicSharedMemorySize, TR_SMEM);

    const int TRB  = (NU + 127) / 128;
    const int AGGB = (NR * 32 + 255) / 256;

    // zeroing via memset nodes (not kernel launches)
    cudaMemsetAsync(deg, 0, M2 * sizeof(int), 0);
    cudaMemsetAsync(cur, 0, M2 * sizeof(int), 0);

    // CSR build: 3 kernels
    k_count  <<<(E_ + 255) / 256, 256>>>(edge_index, deg, E_);          // #1
    k_scan_lb<<<NSCANB, SCAN_B>>>(deg, off_u, off_r, M2, E_);           // #2
    k_fill   <<<(E_ + 255) / 256, 256>>>(edge_index, off_u, off_r, cur,
                                         nbr_u, nbr_r, E_);             // #3

    // #4: agg_r0 (user_emb -> mean_r)  <-- ncu profiles this one
    k_aggregate<<<AGGB, 256>>>(off_r, nbr_r, user_emb, mean_r, NR);

    // #5: init x_recipe
    k_init_recipe<<<(NR * 16 + 255) / 256, 256>>>(recipe_x, lin_w, lin_b,
                                                  recipe_emb, xr0, NR);

    // #6: agg_u0 (xr0 -> mean_u)
    k_aggregate<<<AGGB, 256>>>(off_u, nbr_u, xr0, mean_u, NU);

    // #7-8: layer-0 transforms (relu)
    k_transform<<<TRB, 256, TR_SMEM>>>(mean_r, xr0, Wl, Wr, bl, xr1, NR, 1);
    k_transform<<<TRB, 256, TR_SMEM>>>(mean_u, user_emb, Wl + 4096, Wr + 4096,
                                       bl + 64, xu1, NU, 1);

    // #9-10: layer-1 aggregations
    k_aggregate<<<AGGB, 256>>>(off_u, nbr_u, xr1, mean_u2, NU);
    k_aggregate<<<AGGB, 256>>>(off_r, nbr_r, xu1, mean_r2, NR);

    // #11-12: layer-1 transforms
    k_transform<<<TRB, 256, TR_SMEM>>>(mean_u2, xu1, Wl + 12288, Wr + 12288,
                                       bl + 192, xu2, NU, 0);
    k_transform<<<TRB, 256, TR_SMEM>>>(mean_r2, xr1, Wl + 8192, Wr + 8192,
                                       bl + 128, xr0, NR, 0);

    // #13: classifier
    k_classify<<<(L_ * 16 + 255) / 256, 256>>>(eli, xu2, xr0, out, L_);
}

// round 7
// speedup vs baseline: 1.3831x; 1.3831x over previous
#include <cuda_runtime.h>
#include <cuda_bf16.h>

#define NU 200000
#define NR 200000
#define HDIM 64
#define EDGES 4000000
#define SCAN_B 1024
#define M2 (2 * NU)
#define NSCANB ((M2 + SCAN_B - 1) / SCAN_B)   // 391

typedef unsigned long long ull;
typedef unsigned int uint;

// ---------------- static device scratch ----------------
__device__ float g_xr0[(size_t)NR * HDIM];
__device__ float g_xr1[(size_t)NR * HDIM];
__device__ float g_xu1[(size_t)NU * HDIM];
__device__ float g_xu2[(size_t)NU * HDIM];
__device__ float g_mean_r[(size_t)NR * HDIM];
__device__ float g_mean_u[(size_t)NU * HDIM];
__device__ float g_mean_r2[(size_t)NR * HDIM];
__device__ float g_mean_u2[(size_t)NU * HDIM];
__device__ int   g_nbr_r[EDGES];
__device__ int   g_nbr_u[EDGES];
__device__ int   g_off_u[NU + 1];
__device__ int   g_off_r[NR + 1];
__device__ int   g_deg[M2];
__device__ int   g_cur[M2];
__device__ volatile ull g_scan_state[NSCANB];
// prepped W tiles, per transform: [hi: 64x128 bf16 (16KB)][lo: 64x128 bf16 (16KB)], layout n*128+k
__device__ unsigned char g_bw[4][32768];

// hi/lo bf16 split of a float2, packed as bf16x2 words
__device__ __forceinline__ void split2(float2 f, uint& hi, uint& lo) {
    __nv_bfloat162 h = __float22bfloat162_rn(f);
    float2 hf = __bfloat1622float2(h);
    __nv_bfloat162 l = __float22bfloat162_rn(make_float2(f.x - hf.x, f.y - hf.y));
    hi = *(uint*)&h;
    lo = *(uint*)&l;
}

// m16n8k16 row.col bf16 MMA, fp32 accum (sm_80+ PTX, works on compute_103)
__device__ __forceinline__ void mma16816(float* c, uint a0, uint a1, uint a2, uint a3,
                                         uint b0, uint b1) {
    asm volatile(
        "mma.sync.aligned.m16n8k16.row.col.f32.bf16.bf16.f32 "
        "{%0,%1,%2,%3}, {%4,%5,%6,%7}, {%8,%9}, {%0,%1,%2,%3};"
        : "+f"(c[0]), "+f"(c[1]), "+f"(c[2]), "+f"(c[3])
        : "r"(a0), "r"(a1), "r"(a2), "r"(a3), "r"(b0), "r"(b1));
}

// ---------------- CSR: count (also resets scan state) ----------------
__global__ void k_count(const int* __restrict__ ei, int* __restrict__ deg, int e) {
    if (blockIdx.x == 0 && threadIdx.x < NSCANB)
        *(ull*)&g_scan_state[threadIdx.x] = 0ull;
    int i = blockIdx.x * blockDim.x + threadIdx.x;
    if (i < e) {
        atomicAdd(&deg[ei[i]], 1);
        atomicAdd(&deg[NU + ei[e + i]], 1);
    }
}

// ---------------- CSR: decoupled-lookback scan ----------------
__global__ void __launch_bounds__(SCAN_B) k_scan_lb(
    const int* __restrict__ deg, int* __restrict__ off_u, int* __restrict__ off_r,
    int n, int etot) {
    __shared__ int sh[SCAN_B];
    __shared__ int s_prefix;
    int b = blockIdx.x;
    int i = b * SCAN_B + threadIdx.x;
    int v = (i < n) ? deg[i] : 0;
    sh[threadIdx.x] = v;
    __syncthreads();
    for (int s = 1; s < SCAN_B; s <<= 1) {
        int t = (threadIdx.x >= s) ? sh[threadIdx.x - s] : 0;
        __syncthreads();
        sh[threadIdx.x] += t;
        __syncthreads();
    }
    int incl_local = sh[threadIdx.x];
    int total = sh[SCAN_B - 1];
    if (threadIdx.x == 0) {
        if (b == 0) {
            atomicExch((ull*)&g_scan_state[0], ((ull)2 << 32) | (unsigned)total);
            s_prefix = 0;
        } else {
            atomicExch((ull*)&g_scan_state[b], ((ull)1 << 32) | (unsigned)total);
            int prefix = 0;
            for (int p = b - 1; p >= 0;) {
                ull st;
                do { st = g_scan_state[p]; } while ((st >> 32) == 0);
                prefix += (int)(unsigned)st;
                if ((st >> 32) == 2) break;
                p--;
            }
            atomicExch((ull*)&g_scan_state[b], ((ull)2 << 32) | (unsigned)(prefix + total));
            s_prefix = prefix;
        }
    }
    __syncthreads();
    int excl = s_prefix + incl_local - v;
    if (i < n) {
        if (i < NU) off_u[i] = excl;
        else        off_r[i - NU] = excl - etot;
        if (i == NU) off_u[NU] = excl;
        if (i == n - 1) off_r[NR] = excl + v - etot;
    }
}

__global__ void k_fill(const int* __restrict__ ei,
                       const int* __restrict__ off_u, const int* __restrict__ off_r,
                       int* __restrict__ cur,
                       int* __restrict__ nbr_u, int* __restrict__ nbr_r, int e) {
    int i = blockIdx.x * blockDim.x + threadIdx.x;
    if (i < e) {
        int s = ei[i], d = ei[e + i];
        int pu = atomicAdd(&cur[s], 1);
        nbr_u[off_u[s] + pu] = d;
        int pr = atomicAdd(&cur[NU + d], 1);
        nbr_r[off_r[d] + pr] = s;
    }
}

// ---------------- mean aggregation (at L2 roofline, keep) ----------------
__global__ void __launch_bounds__(256) k_aggregate(
    const int* __restrict__ off, const int* __restrict__ nbr,
    const float* __restrict__ xsrc, float* __restrict__ mean, int n) {
    int w = (blockIdx.x * blockDim.x + threadIdx.x) >> 5;
    int lane = threadIdx.x & 31;
    if (w >= n) return;
    int beg = off[w], end = off[w + 1];
    int half = lane >> 4;
    int hl = lane & 15;
    const float4* X = (const float4*)xsrc;
    float ax = 0.f, ay = 0.f, az = 0.f, aw = 0.f;
    for (int j = beg; j < end; j += 32) {
        int cnt = end - j; if (cnt > 32) cnt = 32;
        int idx = (lane < cnt) ? nbr[j + lane] : 0;
        int t = 0;
        for (; t + 16 <= cnt; t += 16) {
#pragma unroll
            for (int s = 0; s < 8; s++) {
                int r = __shfl_sync(0xffffffffu, idx, t + 2 * s + half);
                float4 v = X[(size_t)r * 16 + hl];
                ax += v.x; ay += v.y; az += v.z; aw += v.w;
            }
        }
        for (; t < cnt; t += 2) {
            int u = t + half;
            int r = __shfl_sync(0xffffffffu, idx, (u < cnt) ? u : t);
            if (u < cnt) {
                float4 v = X[(size_t)r * 16 + hl];
                ax += v.x; ay += v.y; az += v.z; aw += v.w;
            }
        }
    }
    ax += __shfl_down_sync(0xffffffffu, ax, 16);
    ay += __shfl_down_sync(0xffffffffu, ay, 16);
    az += __shfl_down_sync(0xffffffffu, az, 16);
    aw += __shfl_down_sync(0xffffffffu, aw, 16);
    if (lane < 16) {
        float inv = 1.0f / fmaxf((float)(end - beg), 1.0f);
        ((float4*)mean)[(size_t)w * 16 + hl] =
            make_float4(ax * inv, ay * inv, az * inv, aw * inv);
    }
}

// ---------------- weight prep: Wt[n][k] bf16 hi/lo, k<64 -> Wl, k>=64 -> Wr ----------------
__global__ void __launch_bounds__(128) k_prep_w(
    const float* __restrict__ Wl, const float* __restrict__ Wr) {
    const int offs[4] = {0, 4096, 12288, 8192};  // T0:r0 T1:u0 T2:u1 T3:r1
    int b = blockIdx.x;
    int off = offs[b];
    __nv_bfloat16* hi = (__nv_bfloat16*)g_bw[b];
    __nv_bfloat16* lo = hi + 8192;
    for (int i = threadIdx.x; i < 8192; i += 128) {
        int n = i >> 7, k = i & 127;
        float w = (k < 64) ? Wl[off + k * 64 + n] : Wr[off + (k - 64) * 64 + n];
        __nv_bfloat16 h = __float2bfloat16(w);
        hi[i] = h;
        lo[i] = __float2bfloat16(w - __bfloat162float(h));
    }
}

// ---------------- HMMA transform: out = [A0|A1] @ [W0;W1] + bias (+relu) ----------------
// 128-row tile, 256 threads (8 warps x 16-row strips). bf16 3-term split, fp32 accum.
// smem: Ah/Al 128x136 bf16, Bh/Bl 64x136 bf16 (K padded 128->136 for conflict-free LDS).
#define KPAD 136
#define SA_WORDS (128 * (KPAD / 2))   // uint words per A tile: 8704
#define SB_WORDS (64 * (KPAD / 2))    // 4352
#define SM_AH 0
#define SM_AL (SA_WORDS)
#define SM_BH (2 * SA_WORDS)
#define SM_BL (2 * SA_WORDS + SB_WORDS)
#define SM_WORDS (2 * SA_WORDS + 2 * SB_WORDS)   // 26112 words = 104448 B

__global__ void __launch_bounds__(256) k_tmma(
    const float* __restrict__ A0, const float* __restrict__ A1,
    const unsigned char* __restrict__ bw,
    const float* __restrict__ bias, float* __restrict__ out, int n, int relu) {
    extern __shared__ uint smem[];
    uint* ah = smem + SM_AH;
    uint* al = smem + SM_AL;
    uint* bh = smem + SM_BH;
    uint* bl = smem + SM_BL;
    const int tid = threadIdx.x;
    const int rbase = blockIdx.x * 128;

    // load prepped B: hi 4096 uints, lo 4096 uints; insert K pad
    {
        const uint* bs = (const uint*)bw;
#pragma unroll
        for (int it = 0; it < 16; it++) {
            int u = tid + it * 256;            // 0..4095
            int nn = u >> 6, kw = u & 63;
            int d = nn * (KPAD / 2) + kw;
            bh[d] = bs[u];
            bl[d] = bs[4096 + u];
        }
    }

    // convert A = [A0 | A1] fp32 -> bf16 hi/lo
#pragma unroll
    for (int it = 0; it < 16; it++) {
        int idx4 = tid + it * 256;             // 0..4095 float4s (128 rows x 32)
        int r = idx4 >> 5, q = idx4 & 31;      // q<16: A0 cols, else A1
        int gr = rbase + r; if (gr >= n) gr = rbase;
        const float4* sp = (const float4*)((q < 16 ? A0 : A1) + (size_t)gr * 64) + (q & 15);
        float4 v = *sp;
        uint h01, l01, h23, l23;
        split2(make_float2(v.x, v.y), h01, l01);
        split2(make_float2(v.z, v.w), h23, l23);
        int ui = r * (KPAD / 2) + q * 2;       // k = q*4 -> word q*2
        ah[ui] = h01; ah[ui + 1] = h23;
        al[ui] = l01; al[ui + 1] = l23;
    }
    __syncthreads();

    // mainloop: warp w owns rows [w*16, w*16+16)
    const int wid = tid >> 5, lane = tid & 31;
    const int g = lane >> 2, tg = lane & 3;
    const int rowA = wid * 16 + g;
    const int rowA8 = rowA + 8;

    float acc[8][4];
#pragma unroll
    for (int j = 0; j < 8; j++)
#pragma unroll
        for (int q = 0; q < 4; q++) acc[j][q] = 0.f;

#pragma unroll
    for (int kk = 0; kk < 8; kk++) {
        int kw = kk * 8 + tg;                  // uint word index within row (k = kw*2)
        uint ah0 = ah[rowA * (KPAD / 2) + kw];
        uint ah1 = ah[rowA8 * (KPAD / 2) + kw];
        uint ah2 = ah[rowA * (KPAD / 2) + kw + 4];
        uint ah3 = ah[rowA8 * (KPAD / 2) + kw + 4];
        uint al0 = al[rowA * (KPAD / 2) + kw];
        uint al1 = al[rowA8 * (KPAD / 2) + kw];
        uint al2 = al[rowA * (KPAD / 2) + kw + 4];
        uint al3 = al[rowA8 * (KPAD / 2) + kw + 4];
#pragma unroll
        for (int j = 0; j < 8; j++) {
            int nrow = j * 8 + g;
            uint bh0 = bh[nrow * (KPAD / 2) + kw];
            uint bh1 = bh[nrow * (KPAD / 2) + kw + 4];
            uint bl0 = bl[nrow * (KPAD / 2) + kw];
            uint bl1 = bl[nrow * (KPAD / 2) + kw + 4];
            mma16816(acc[j], ah0, ah1, ah2, ah3, bh0, bh1);   // Ah*Bh
            mma16816(acc[j], al0, al1, al2, al3, bh0, bh1);   // Al*Bh
            mma16816(acc[j], ah0, ah1, ah2, ah3, bl0, bl1);   // Ah*Bl
        }
    }

    // epilogue: D row = rbase + rowA (+8), cols j*8 + tg*2, tg*2+1
    int row1 = rbase + rowA;
    int row2 = row1 + 8;
#pragma unroll
    for (int j = 0; j < 8; j++) {
        int col = j * 8 + tg * 2;
        float2 bb = *(const float2*)(bias + col);
        float2 o1 = make_float2(acc[j][0] + bb.x, acc[j][1] + bb.y);
        float2 o2 = make_float2(acc[j][2] + bb.x, acc[j][3] + bb.y);
        if (relu) {
            o1.x = fmaxf(o1.x, 0.f); o1.y = fmaxf(o1.y, 0.f);
            o2.x = fmaxf(o2.x, 0.f); o2.y = fmaxf(o2.y, 0.f);
        }
        if (row1 < n) *(float2*)(out + (size_t)row1 * 64 + col) = o1;
        if (row2 < n) *(float2*)(out + (size_t)row2 * 64 + col) = o2;
    }
}

// ---------------- x_recipe init ----------------
__global__ void __launch_bounds__(256) k_init_recipe(
    const float* __restrict__ rx, const float* __restrict__ lw,
    const float* __restrict__ lb, const float* __restrict__ remb,
    float* __restrict__ xout, int n) {
    __shared__ float slw[640];
    __shared__ float slb[64];
    int t = threadIdx.x;
    for (int i = t; i < 640; i += 256) slw[i] = lw[i];
    if (t < 64) slb[t] = lb[t];
    __syncthreads();
    int idx4 = blockIdx.x * 256 + t;
    if (idx4 >= n * 16) return;
    int r = idx4 >> 4;
    int h0 = (idx4 & 15) * 4;
    float4 acc = make_float4(slb[h0], slb[h0 + 1], slb[h0 + 2], slb[h0 + 3]);
    const float* xr = rx + r * 10;
#pragma unroll
    for (int k = 0; k < 10; k++) {
        float xv = xr[k];
        const float* wr = slw + k * 64 + h0;
        acc.x = fmaf(xv, wr[0], acc.x);
        acc.y = fmaf(xv, wr[1], acc.y);
        acc.z = fmaf(xv, wr[2], acc.z);
        acc.w = fmaf(xv, wr[3], acc.w);
    }
    float4 e = ((const float4*)remb)[idx4];
    acc.x += e.x; acc.y += e.y; acc.z += e.z; acc.w += e.w;
    ((float4*)xout)[idx4] = acc;
}

// ---------------- classifier: half-warp per label edge ----------------
__global__ void __launch_bounds__(256) k_classify(
    const int* __restrict__ eli, const float* __restrict__ xu,
    const float* __restrict__ xr, float* __restrict__ out, int nl) {
    int hw = (blockIdx.x * blockDim.x + threadIdx.x) >> 4;
    int hl = threadIdx.x & 15;
    if (hw >= nl) return;
    int a = eli[hw], b = eli[nl + hw];
    float4 va = ((const float4*)xu)[(size_t)a * 16 + hl];
    float4 vb = ((const float4*)xr)[(size_t)b * 16 + hl];
    float s = va.x * vb.x + va.y * vb.y + va.z * vb.z + va.w * vb.w;
    s += __shfl_down_sync(0xffffffffu, s, 8, 16);
    s += __shfl_down_sync(0xffffffffu, s, 4, 16);
    s += __shfl_down_sync(0xffffffffu, s, 2, 16);
    s += __shfl_down_sync(0xffffffffu, s, 1, 16);
    if (hl == 0) out[hw] = s;
}

// ---------------- launch ----------------
extern "C" void kernel_launch(void* const* d_in, const int* in_sizes, int n_in,
                              void* d_out, int out_size) {
    const float* recipe_x   = (const float*)d_in[2];
    const int*   edge_index = (const int*)d_in[3];
    const int*   eli        = (const int*)d_in[4];
    const float* user_emb   = (const float*)d_in[5];
    const float* recipe_emb = (const float*)d_in[6];
    const float* lin_w      = (const float*)d_in[7];
    const float* lin_b      = (const float*)d_in[8];
    const float* Wl         = (const float*)d_in[9];
    const float* bl         = (const float*)d_in[10];
    const float* Wr         = (const float*)d_in[11];
    float* out = (float*)d_out;
    int E_ = in_sizes[3] / 2;
    int L_ = in_sizes[4] / 2;

    float *xr0, *xr1, *xu1, *xu2, *mean_r, *mean_u, *mean_r2, *mean_u2;
    int *nbr_r, *nbr_u, *off_u, *off_r, *deg, *cur;
    unsigned char* bw;
    cudaGetSymbolAddress((void**)&xr0,     g_xr0);
    cudaGetSymbolAddress((void**)&xr1,     g_xr1);
    cudaGetSymbolAddress((void**)&xu1,     g_xu1);
    cudaGetSymbolAddress((void**)&xu2,     g_xu2);
    cudaGetSymbolAddress((void**)&mean_r,  g_mean_r);
    cudaGetSymbolAddress((void**)&mean_u,  g_mean_u);
    cudaGetSymbolAddress((void**)&mean_r2, g_mean_r2);
    cudaGetSymbolAddress((void**)&mean_u2, g_mean_u2);
    cudaGetSymbolAddress((void**)&nbr_r,   g_nbr_r);
    cudaGetSymbolAddress((void**)&nbr_u,   g_nbr_u);
    cudaGetSymbolAddress((void**)&off_u,   g_off_u);
    cudaGetSymbolAddress((void**)&off_r,   g_off_r);
    cudaGetSymbolAddress((void**)&deg,     g_deg);
    cudaGetSymbolAddress((void**)&cur,     g_cur);
    cudaGetSymbolAddress((void**)&bw,      g_bw);

    const int TM_SMEM = SM_WORDS * 4;   // 104448 B
    cudaFuncSetAttribute(k_tmma, cudaFuncAttributeMaxDynamicSharedMemorySize, TM_SMEM);

    const int TMB  = (NU + 127) / 128;          // 1563
    const int AGGB = (NR * 32 + 255) / 256;

    cudaMemsetAsync(deg, 0, M2 * sizeof(int), 0);
    cudaMemsetAsync(cur, 0, M2 * sizeof(int), 0);

    // CSR build (kernels #1-3)
    k_count  <<<(E_ + 255) / 256, 256>>>(edge_index, deg, E_);
    k_scan_lb<<<NSCANB, SCAN_B>>>(deg, off_u, off_r, M2, E_);
    k_fill   <<<(E_ + 255) / 256, 256>>>(edge_index, off_u, off_r, cur,
                                         nbr_u, nbr_r, E_);

    // #4: agg_r0 (profiled)
    k_aggregate<<<AGGB, 256>>>(off_r, nbr_r, user_emb, mean_r, NR);

    // #5: weight prep; #6: x_recipe init
    k_prep_w<<<4, 128>>>(Wl, Wr);
    k_init_recipe<<<(NR * 16 + 255) / 256, 256>>>(recipe_x, lin_w, lin_b,
                                                  recipe_emb, xr0, NR);

    // #7: agg_u0
    k_aggregate<<<AGGB, 256>>>(off_u, nbr_u, xr0, mean_u, NU);

    // #8-9: layer-0 transforms (relu)
    k_tmma<<<TMB, 256, TM_SMEM>>>(mean_r, xr0, bw + 0 * 32768, bl,       xr1, NR, 1);
    k_tmma<<<TMB, 256, TM_SMEM>>>(mean_u, user_emb, bw + 1 * 32768, bl + 64, xu1, NU, 1);

    // #10-11: layer-1 aggregations
    k_aggregate<<<AGGB, 256>>>(off_u, nbr_u, xr1, mean_u2, NU);
    k_aggregate<<<AGGB, 256>>>(off_r, nbr_r, xu1, mean_r2, NR);

    // #12-13: layer-1 transforms
    k_tmma<<<TMB, 256, TM_SMEM>>>(mean_u2, xu1, bw + 2 * 32768, bl + 192, xu2, NU, 0);
    k_tmma<<<TMB, 256, TM_SMEM>>>(mean_r2, xr1, bw + 3 * 32768, bl + 128, xr0, NR, 0);

    // #14: classifier
    k_classify<<<(L_ * 16 + 255) / 256, 256>>>(eli, xu2, xr0, out, L_);
}

// round 8
// speedup vs baseline: 1.5247x; 1.1024x over previous
#include <cuda_runtime.h>
#include <cuda_bf16.h>
#include <cuda_fp16.h>

#define NU 200000
#define NR 200000
#define HDIM 64
#define EDGES 4000000
#define SCAN_B 1024
#define M2 (2 * NU)
#define NSCANB ((M2 + SCAN_B - 1) / SCAN_B)   // 391

typedef unsigned long long ull;
typedef unsigned int uint;

// ---------------- static device scratch ----------------
__device__ float g_xr0[(size_t)NR * HDIM];
__device__ float g_xr1[(size_t)NR * HDIM];
__device__ float g_xu1[(size_t)NU * HDIM];
__device__ float g_xu2[(size_t)NU * HDIM];
__device__ float g_mean_r[(size_t)NR * HDIM];
__device__ float g_mean_u[(size_t)NU * HDIM];
__device__ float g_mean_r2[(size_t)NR * HDIM];
__device__ float g_mean_u2[(size_t)NU * HDIM];
__device__ __half g_uh16 [(size_t)NU * HDIM];   // fp16 mirrors for gathering
__device__ __half g_xr0h [(size_t)NR * HDIM];
__device__ __half g_xr1h [(size_t)NR * HDIM];
__device__ __half g_xu1h [(size_t)NU * HDIM];
__device__ int   g_nbr_r[EDGES];
__device__ int   g_nbr_u[EDGES];
__device__ int   g_off_u[NU + 1];
__device__ int   g_off_r[NR + 1];
__device__ int   g_deg[M2];
__device__ int   g_cur[M2];
__device__ volatile ull g_scan_state[NSCANB];
// prepped W tiles, per transform: [hi: 64x128 bf16 (16KB)][lo: 64x128 bf16 (16KB)], layout n*128+k
__device__ unsigned char g_bw[4][32768];

// hi/lo bf16 split of a float2, packed as bf16x2 words
__device__ __forceinline__ void split2(float2 f, uint& hi, uint& lo) {
    __nv_bfloat162 h = __float22bfloat162_rn(f);
    float2 hf = __bfloat1622float2(h);
    __nv_bfloat162 l = __float22bfloat162_rn(make_float2(f.x - hf.x, f.y - hf.y));
    hi = *(uint*)&h;
    lo = *(uint*)&l;
}

// m16n8k16 row.col bf16 MMA, fp32 accum
__device__ __forceinline__ void mma16816(float* c, uint a0, uint a1, uint a2, uint a3,
                                         uint b0, uint b1) {
    asm volatile(
        "mma.sync.aligned.m16n8k16.row.col.f32.bf16.bf16.f32 "
        "{%0,%1,%2,%3}, {%4,%5,%6,%7}, {%8,%9}, {%0,%1,%2,%3};"
        : "+f"(c[0]), "+f"(c[1]), "+f"(c[2]), "+f"(c[3])
        : "r"(a0), "r"(a1), "r"(a2), "r"(a3), "r"(b0), "r"(b1));
}

// ---------------- CSR: count + reset scan state + convert user_emb to fp16 ----------------
__global__ void k_count(const int* __restrict__ ei, int* __restrict__ deg,
                        const float* __restrict__ ue, int e) {
    int i = blockIdx.x * blockDim.x + threadIdx.x;
    if (blockIdx.x == 0 && threadIdx.x < NSCANB)
        *(ull*)&g_scan_state[threadIdx.x] = 0ull;
    if (i < NU * 16) {   // 3.2M float4s
        float4 v = ((const float4*)ue)[i];
        __half2 h0 = __floats2half2_rn(v.x, v.y);
        __half2 h1 = __floats2half2_rn(v.z, v.w);
        ((uint2*)g_uh16)[i] = make_uint2(*(uint*)&h0, *(uint*)&h1);
    }
    if (i < e) {
        atomicAdd(&deg[ei[i]], 1);
        atomicAdd(&deg[NU + ei[e + i]], 1);
    }
}

// ---------------- CSR: decoupled-lookback scan ----------------
__global__ void __launch_bounds__(SCAN_B) k_scan_lb(
    const int* __restrict__ deg, int* __restrict__ off_u, int* __restrict__ off_r,
    int n, int etot) {
    __shared__ int sh[SCAN_B];
    __shared__ int s_prefix;
    int b = blockIdx.x;
    int i = b * SCAN_B + threadIdx.x;
    int v = (i < n) ? deg[i] : 0;
    sh[threadIdx.x] = v;
    __syncthreads();
    for (int s = 1; s < SCAN_B; s <<= 1) {
        int t = (threadIdx.x >= s) ? sh[threadIdx.x - s] : 0;
        __syncthreads();
        sh[threadIdx.x] += t;
        __syncthreads();
    }
    int incl_local = sh[threadIdx.x];
    int total = sh[SCAN_B - 1];
    if (threadIdx.x == 0) {
        if (b == 0) {
            atomicExch((ull*)&g_scan_state[0], ((ull)2 << 32) | (unsigned)total);
            s_prefix = 0;
        } else {
            atomicExch((ull*)&g_scan_state[b], ((ull)1 << 32) | (unsigned)total);
            int prefix = 0;
            for (int p = b - 1; p >= 0;) {
                ull st;
                do { st = g_scan_state[p]; } while ((st >> 32) == 0);
                prefix += (int)(unsigned)st;
                if ((st >> 32) == 2) break;
                p--;
            }
            atomicExch((ull*)&g_scan_state[b], ((ull)2 << 32) | (unsigned)(prefix + total));
            s_prefix = prefix;
        }
    }
    __syncthreads();
    int excl = s_prefix + incl_local - v;
    if (i < n) {
        if (i < NU) off_u[i] = excl;
        else        off_r[i - NU] = excl - etot;
        if (i == NU) off_u[NU] = excl;
        if (i == n - 1) off_r[NR] = excl + v - etot;
    }
}

__global__ void k_fill(const int* __restrict__ ei,
                       const int* __restrict__ off_u, const int* __restrict__ off_r,
                       int* __restrict__ cur,
                       int* __restrict__ nbr_u, int* __restrict__ nbr_r, int e) {
    int i = blockIdx.x * blockDim.x + threadIdx.x;
    if (i < e) {
        int s = ei[i], d = ei[e + i];
        int pu = atomicAdd(&cur[s], 1);
        nbr_u[off_u[s] + pu] = d;
        int pr = atomicAdd(&cur[NU + d], 1);
        nbr_r[off_r[d] + pr] = s;
    }
}

// ---------------- fp16 mean aggregation: warp per node, 8 lanes per neighbor row ----
__global__ void __launch_bounds__(256) k_aggregate_h(
    const int* __restrict__ off, const int* __restrict__ nbr,
    const __half* __restrict__ xsrc, float* __restrict__ mean, int n) {
    int w = (blockIdx.x * blockDim.x + threadIdx.x) >> 5;
    int lane = threadIdx.x & 31;
    if (w >= n) return;
    int beg = off[w], end = off[w + 1];
    int q = lane >> 3;       // neighbor slot 0..3
    int c = lane & 7;        // 16B chunk within 128B row
    const uint4* X = (const uint4*)xsrc;   // row = 8 uint4
    float a[8];
#pragma unroll
    for (int i = 0; i < 8; i++) a[i] = 0.f;

    for (int j = beg; j < end; j += 32) {
        int cnt = end - j; if (cnt > 32) cnt = 32;
        int idx = (lane < cnt) ? nbr[j + lane] : 0;
        int t = 0;
        for (; t + 8 <= cnt; t += 8) {
            int r0 = __shfl_sync(0xffffffffu, idx, t + q);
            int r1 = __shfl_sync(0xffffffffu, idx, t + 4 + q);
            uint4 v0 = X[(size_t)r0 * 8 + c];
            uint4 v1 = X[(size_t)r1 * 8 + c];
#pragma unroll
            for (int p = 0; p < 4; p++) {
                uint uw0 = (&v0.x)[p], uw1 = (&v1.x)[p];
                float2 f0 = __half22float2(*(__half2*)&uw0);
                float2 f1 = __half22float2(*(__half2*)&uw1);
                a[2 * p]     += f0.x + f1.x;
                a[2 * p + 1] += f0.y + f1.y;
            }
        }
        for (; t < cnt; t += 4) {
            int u = t + q;
            int r = __shfl_sync(0xffffffffu, idx, (u < cnt) ? u : t);
            if (u < cnt) {
                uint4 v = X[(size_t)r * 8 + c];
#pragma unroll
                for (int p = 0; p < 4; p++) {
                    uint uw = (&v.x)[p];
                    float2 f = __half22float2(*(__half2*)&uw);
                    a[2 * p]     += f.x;
                    a[2 * p + 1] += f.y;
                }
            }
        }
    }
    // fold neighbor slots q=0..3 (lanes 0-7 end with totals)
#pragma unroll
    for (int i = 0; i < 8; i++) {
        a[i] += __shfl_down_sync(0xffffffffu, a[i], 16);
        a[i] += __shfl_down_sync(0xffffffffu, a[i], 8);
    }
    if (lane < 8) {
        float inv = 1.0f / fmaxf((float)(end - beg), 1.0f);
        float4* mp = (float4*)(mean + (size_t)w * 64 + c * 8);
        mp[0] = make_float4(a[0] * inv, a[1] * inv, a[2] * inv, a[3] * inv);
        mp[1] = make_float4(a[4] * inv, a[5] * inv, a[6] * inv, a[7] * inv);
    }
}

// ---------------- weight prep: Wt[n][k] bf16 hi/lo ----------------
__global__ void __launch_bounds__(128) k_prep_w(
    const float* __restrict__ Wl, const float* __restrict__ Wr) {
    const int offs[4] = {0, 4096, 12288, 8192};  // T0:r0 T1:u0 T2:u1 T3:r1
    int b = blockIdx.x;
    int off = offs[b];
    __nv_bfloat16* hi = (__nv_bfloat16*)g_bw[b];
    __nv_bfloat16* lo = hi + 8192;
    for (int i = threadIdx.x; i < 8192; i += 128) {
        int n = i >> 7, k = i & 127;
        float w = (k < 64) ? Wl[off + k * 64 + n] : Wr[off + (k - 64) * 64 + n];
        __nv_bfloat16 h = __float2bfloat16(w);
        hi[i] = h;
        lo[i] = __float2bfloat16(w - __bfloat162float(h));
    }
}

// ---------------- HMMA transform ----------------
#define KPAD 136
#define SA_WORDS (128 * (KPAD / 2))
#define SB_WORDS (64 * (KPAD / 2))
#define SM_AH 0
#define SM_AL (SA_WORDS)
#define SM_BH (2 * SA_WORDS)
#define SM_BL (2 * SA_WORDS + SB_WORDS)
#define SM_WORDS (2 * SA_WORDS + 2 * SB_WORDS)   // 104448 B

__global__ void __launch_bounds__(256) k_tmma(
    const float* __restrict__ A0, const float* __restrict__ A1,
    const unsigned char* __restrict__ bw,
    const float* __restrict__ bias, float* __restrict__ out,
    __half* __restrict__ out16, int n, int relu) {
    extern __shared__ uint smem[];
    uint* ah = smem + SM_AH;
    uint* al = smem + SM_AL;
    uint* bh = smem + SM_BH;
    uint* bl = smem + SM_BL;
    const int tid = threadIdx.x;
    const int rbase = blockIdx.x * 128;

    {
        const uint* bs = (const uint*)bw;
#pragma unroll
        for (int it = 0; it < 16; it++) {
            int u = tid + it * 256;
            int nn = u >> 6, kw = u & 63;
            int d = nn * (KPAD / 2) + kw;
            bh[d] = bs[u];
            bl[d] = bs[4096 + u];
        }
    }

#pragma unroll
    for (int it = 0; it < 16; it++) {
        int idx4 = tid + it * 256;
        int r = idx4 >> 5, qq = idx4 & 31;
        int gr = rbase + r; if (gr >= n) gr = rbase;
        const float4* sp = (const float4*)((qq < 16 ? A0 : A1) + (size_t)gr * 64) + (qq & 15);
        float4 v = *sp;
        uint h01, l01, h23, l23;
        split2(make_float2(v.x, v.y), h01, l01);
        split2(make_float2(v.z, v.w), h23, l23);
        int ui = r * (KPAD / 2) + qq * 2;
        ah[ui] = h01; ah[ui + 1] = h23;
        al[ui] = l01; al[ui + 1] = l23;
    }
    __syncthreads();

    const int wid = tid >> 5, lane = tid & 31;
    const int g = lane >> 2, tg = lane & 3;
    const int rowA = wid * 16 + g;
    const int rowA8 = rowA + 8;

    float acc[8][4];
#pragma unroll
    for (int j = 0; j < 8; j++)
#pragma unroll
        for (int q = 0; q < 4; q++) acc[j][q] = 0.f;

#pragma unroll
    for (int kk = 0; kk < 8; kk++) {
        int kw = kk * 8 + tg;
        uint ah0 = ah[rowA * (KPAD / 2) + kw];
        uint ah1 = ah[rowA8 * (KPAD / 2) + kw];
        uint ah2 = ah[rowA * (KPAD / 2) + kw + 4];
        uint ah3 = ah[rowA8 * (KPAD / 2) + kw + 4];
        uint al0 = al[rowA * (KPAD / 2) + kw];
        uint al1 = al[rowA8 * (KPAD / 2) + kw];
        uint al2 = al[rowA * (KPAD / 2) + kw + 4];
        uint al3 = al[rowA8 * (KPAD / 2) + kw + 4];
#pragma unroll
        for (int j = 0; j < 8; j++) {
            int nrow = j * 8 + g;
            uint bh0 = bh[nrow * (KPAD / 2) + kw];
            uint bh1 = bh[nrow * (KPAD / 2) + kw + 4];
            uint bl0 = bl[nrow * (KPAD / 2) + kw];
            uint bl1 = bl[nrow * (KPAD / 2) + kw + 4];
            mma16816(acc[j], ah0, ah1, ah2, ah3, bh0, bh1);
            mma16816(acc[j], al0, al1, al2, al3, bh0, bh1);
            mma16816(acc[j], ah0, ah1, ah2, ah3, bl0, bl1);
        }
    }

    int row1 = rbase + rowA;
    int row2 = row1 + 8;
#pragma unroll
    for (int j = 0; j < 8; j++) {
        int col = j * 8 + tg * 2;
        float2 bb = *(const float2*)(bias + col);
        float2 o1 = make_float2(acc[j][0] + bb.x, acc[j][1] + bb.y);
        float2 o2 = make_float2(acc[j][2] + bb.x, acc[j][3] + bb.y);
        if (relu) {
            o1.x = fmaxf(o1.x, 0.f); o1.y = fmaxf(o1.y, 0.f);
            o2.x = fmaxf(o2.x, 0.f); o2.y = fmaxf(o2.y, 0.f);
        }
        if (row1 < n) {
            *(float2*)(out + (size_t)row1 * 64 + col) = o1;
            if (out16) {
                __half2 p = __floats2half2_rn(o1.x, o1.y);
                *(__half2*)(out16 + (size_t)row1 * 64 + col) = p;
            }
        }
        if (row2 < n) {
            *(float2*)(out + (size_t)row2 * 64 + col) = o2;
            if (out16) {
                __half2 p = __floats2half2_rn(o2.x, o2.y);
                *(__half2*)(out16 + (size_t)row2 * 64 + col) = p;
            }
        }
    }
}

// ---------------- x_recipe init (writes fp32 + fp16) ----------------
__global__ void __launch_bounds__(256) k_init_recipe(
    const float* __restrict__ rx, const float* __restrict__ lw,
    const float* __restrict__ lb, const float* __restrict__ remb,
    float* __restrict__ xout, __half* __restrict__ xout16, int n) {
    __shared__ float slw[640];
    __shared__ float slb[64];
    int t = threadIdx.x;
    for (int i = t; i < 640; i += 256) slw[i] = lw[i];
    if (t < 64) slb[t] = lb[t];
    __syncthreads();
    int idx4 = blockIdx.x * 256 + t;
    if (idx4 >= n * 16) return;
    int r = idx4 >> 4;
    int h0 = (idx4 & 15) * 4;
    float4 acc = make_float4(slb[h0], slb[h0 + 1], slb[h0 + 2], slb[h0 + 3]);
    const float* xr = rx + r * 10;
#pragma unroll
    for (int k = 0; k < 10; k++) {
        float xv = xr[k];
        const float* wr = slw + k * 64 + h0;
        acc.x = fmaf(xv, wr[0], acc.x);
        acc.y = fmaf(xv, wr[1], acc.y);
        acc.z = fmaf(xv, wr[2], acc.z);
        acc.w = fmaf(xv, wr[3], acc.w);
    }
    float4 e = ((const float4*)remb)[idx4];
    acc.x += e.x; acc.y += e.y; acc.z += e.z; acc.w += e.w;
    ((float4*)xout)[idx4] = acc;
    __half2 ha = __floats2half2_rn(acc.x, acc.y);
    __half2 hb = __floats2half2_rn(acc.z, acc.w);
    ((uint2*)xout16)[idx4] = make_uint2(*(uint*)&ha, *(uint*)&hb);
}

// ---------------- classifier: half-warp per label edge (fp32 finals) ----------------
__global__ void __launch_bounds__(256) k_classify(
    const int* __restrict__ eli, const float* __restrict__ xu,
    const float* __restrict__ xr, float* __restrict__ out, int nl) {
    int hw = (blockIdx.x * blockDim.x + threadIdx.x) >> 4;
    int hl = threadIdx.x & 15;
    if (hw >= nl) return;
    int a = eli[hw], b = eli[nl + hw];
    float4 va = ((const float4*)xu)[(size_t)a * 16 + hl];
    float4 vb = ((const float4*)xr)[(size_t)b * 16 + hl];
    float s = va.x * vb.x + va.y * vb.y + va.z * vb.z + va.w * vb.w;
    s += __shfl_down_sync(0xffffffffu, s, 8, 16);
    s += __shfl_down_sync(0xffffffffu, s, 4, 16);
    s += __shfl_down_sync(0xffffffffu, s, 2, 16);
    s += __shfl_down_sync(0xffffffffu, s, 1, 16);
    if (hl == 0) out[hw] = s;
}

// ---------------- launch ----------------
extern "C" void kernel_launch(void* const* d_in, const int* in_sizes, int n_in,
                              void* d_out, int out_size) {
    const float* recipe_x   = (const float*)d_in[2];
    const int*   edge_index = (const int*)d_in[3];
    const int*   eli        = (const int*)d_in[4];
    const float* user_emb   = (const float*)d_in[5];
    const float* recipe_emb = (const float*)d_in[6];
    const float* lin_w      = (const float*)d_in[7];
    const float* lin_b      = (const float*)d_in[8];
    const float* Wl         = (const float*)d_in[9];
    const float* bl         = (const float*)d_in[10];
    const float* Wr         = (const float*)d_in[11];
    float* out = (float*)d_out;
    int E_ = in_sizes[3] / 2;
    int L_ = in_sizes[4] / 2;

    float *xr0, *xr1, *xu1, *xu2, *mean_r, *mean_u, *mean_r2, *mean_u2;
    __half *uh16, *xr0h, *xr1h, *xu1h;
    int *nbr_r, *nbr_u, *off_u, *off_r, *deg, *cur;
    unsigned char* bw;
    cudaGetSymbolAddress((void**)&xr0,     g_xr0);
    cudaGetSymbolAddress((void**)&xr1,     g_xr1);
    cudaGetSymbolAddress((void**)&xu1,     g_xu1);
    cudaGetSymbolAddress((void**)&xu2,     g_xu2);
    cudaGetSymbolAddress((void**)&mean_r,  g_mean_r);
    cudaGetSymbolAddress((void**)&mean_u,  g_mean_u);
    cudaGetSymbolAddress((void**)&mean_r2, g_mean_r2);
    cudaGetSymbolAddress((void**)&mean_u2, g_mean_u2);
    cudaGetSymbolAddress((void**)&uh16,    g_uh16);
    cudaGetSymbolAddress((void**)&xr0h,    g_xr0h);
    cudaGetSymbolAddress((void**)&xr1h,    g_xr1h);
    cudaGetSymbolAddress((void**)&xu1h,    g_xu1h);
    cudaGetSymbolAddress((void**)&nbr_r,   g_nbr_r);
    cudaGetSymbolAddress((void**)&nbr_u,   g_nbr_u);
    cudaGetSymbolAddress((void**)&off_u,   g_off_u);
    cudaGetSymbolAddress((void**)&off_r,   g_off_r);
    cudaGetSymbolAddress((void**)&deg,     g_deg);
    cudaGetSymbolAddress((void**)&cur,     g_cur);
    cudaGetSymbolAddress((void**)&bw,      g_bw);

    const int TM_SMEM = SM_WORDS * 4;
    cudaFuncSetAttribute(k_tmma, cudaFuncAttributeMaxDynamicSharedMemorySize, TM_SMEM);

    const int TMB  = (NU + 127) / 128;
    const int AGGB = (NR * 32 + 255) / 256;

    cudaMemsetAsync(deg, 0, M2 * sizeof(int), 0);
    cudaMemsetAsync(cur, 0, M2 * sizeof(int), 0);

    // CSR build (+ user_emb fp16 mirror inside k_count)
    k_count  <<<(E_ + 255) / 256, 256>>>(edge_index, deg, user_emb, E_);   // #1
    k_scan_lb<<<NSCANB, SCAN_B>>>(deg, off_u, off_r, M2, E_);              // #2
    k_fill   <<<(E_ + 255) / 256, 256>>>(edge_index, off_u, off_r, cur,
                                         nbr_u, nbr_r, E_);                // #3

    // #4: agg_r0 (fp16 gather, profiled)
    k_aggregate_h<<<AGGB, 256>>>(off_r, nbr_r, uh16, mean_r, NR);

    // #5: weight prep; #6: x_recipe init (fp32 + fp16)
    k_prep_w<<<4, 128>>>(Wl, Wr);
    k_init_recipe<<<(NR * 16 + 255) / 256, 256>>>(recipe_x, lin_w, lin_b,
                                                  recipe_emb, xr0, xr0h, NR);

    // #7: agg_u0
    k_aggregate_h<<<AGGB, 256>>>(off_u, nbr_u, xr0h, mean_u, NU);

    // #8-9: layer-0 transforms (relu, dual-store fp16)
    k_tmma<<<TMB, 256, TM_SMEM>>>(mean_r, xr0, bw + 0 * 32768, bl,      xr1, xr1h, NR, 1);
    k_tmma<<<TMB, 256, TM_SMEM>>>(mean_u, user_emb, bw + 1 * 32768, bl + 64, xu1, xu1h, NU, 1);

    // #10-11: layer-1 aggregations (fp16 gather)
    k_aggregate_h<<<AGGB, 256>>>(off_u, nbr_u, xr1h, mean_u2, NU);
    k_aggregate_h<<<AGGB, 256>>>(off_r, nbr_r, xu1h, mean_r2, NR);

    // #12-13: layer-1 transforms (fp32 only)
    k_tmma<<<TMB, 256, TM_SMEM>>>(mean_u2, xu1, bw + 2 * 32768, bl + 192, xu2, (__half*)0, NU, 0);
    k_tmma<<<TMB, 256, TM_SMEM>>>(mean_r2, xr1, bw + 3 * 32768, bl + 128, xr0, (__half*)0, NR, 0);

    // #14: classifier
    k_classify<<<(L_ * 16 + 255) / 256, 256>>>(eli, xu2, xr0, out, L_);
}

// round 9
// speedup vs baseline: 1.5756x; 1.0334x over previous
#include <cuda_runtime.h>
#include <cuda_bf16.h>
#include <cuda_fp16.h>

#define NU 200000
#define NR 200000
#define HDIM 64
#define EDGES 4000000
#define SCAN_B 1024
#define M2 (2 * NU)
#define NSCANB ((M2 + SCAN_B - 1) / SCAN_B)   // 391

typedef unsigned long long ull;
typedef unsigned int uint;

// ---------------- static device scratch ----------------
__device__ float g_xr0[(size_t)NR * HDIM];
__device__ float g_xr1[(size_t)NR * HDIM];
__device__ float g_xu1[(size_t)NU * HDIM];
__device__ float g_xu2[(size_t)NU * HDIM];
__device__ float g_mean_r[(size_t)NR * HDIM];
__device__ float g_mean_u[(size_t)NU * HDIM];
__device__ float g_mean_r2[(size_t)NR * HDIM];
__device__ float g_mean_u2[(size_t)NU * HDIM];
__device__ __half g_uh16 [(size_t)NU * HDIM];   // fp16 mirrors for gathering
__device__ __half g_xr0h [(size_t)NR * HDIM];
__device__ __half g_xr1h [(size_t)NR * HDIM];
__device__ __half g_xu1h [(size_t)NU * HDIM];
__device__ int   g_nbr_r[EDGES];
__device__ int   g_nbr_u[EDGES];
__device__ int   g_off_u[NU + 1];
__device__ int   g_off_r[NR + 1];
__device__ int   g_deg[M2];
__device__ int   g_cur[M2];
__device__ volatile ull g_scan_state[NSCANB];
// prepped W tiles, per transform: [hi: 64x128 bf16 (16KB)][lo: 64x128 bf16 (16KB)], layout n*128+k
__device__ unsigned char g_bw[4][32768];

// hi/lo bf16 split of a float2, packed as bf16x2 words
__device__ __forceinline__ void split2(float2 f, uint& hi, uint& lo) {
    __nv_bfloat162 h = __float22bfloat162_rn(f);
    float2 hf = __bfloat1622float2(h);
    __nv_bfloat162 l = __float22bfloat162_rn(make_float2(f.x - hf.x, f.y - hf.y));
    hi = *(uint*)&h;
    lo = *(uint*)&l;
}

// m16n8k16 row.col bf16 MMA, fp32 accum
__device__ __forceinline__ void mma16816(float* c, uint a0, uint a1, uint a2, uint a3,
                                         uint b0, uint b1) {
    asm volatile(
        "mma.sync.aligned.m16n8k16.row.col.f32.bf16.bf16.f32 "
        "{%0,%1,%2,%3}, {%4,%5,%6,%7}, {%8,%9}, {%0,%1,%2,%3};"
        : "+f"(c[0]), "+f"(c[1]), "+f"(c[2]), "+f"(c[3])
        : "r"(a0), "r"(a1), "r"(a2), "r"(a3), "r"(b0), "r"(b1));
}

// ---------------- CSR: count + reset scan state + convert user_emb to fp16 ----------------
__global__ void k_count(const int* __restrict__ ei, int* __restrict__ deg,
                        const float* __restrict__ ue, int e) {
    int i = blockIdx.x * blockDim.x + threadIdx.x;
    if (blockIdx.x == 0 && threadIdx.x < NSCANB)
        *(ull*)&g_scan_state[threadIdx.x] = 0ull;
    if (i < NU * 16) {   // 3.2M float4s
        float4 v = ((const float4*)ue)[i];
        __half2 h0 = __floats2half2_rn(v.x, v.y);
        __half2 h1 = __floats2half2_rn(v.z, v.w);
        ((uint2*)g_uh16)[i] = make_uint2(*(uint*)&h0, *(uint*)&h1);
    }
    if (i < e) {
        atomicAdd(&deg[ei[i]], 1);
        atomicAdd(&deg[NU + ei[e + i]], 1);
    }
}

// ---------------- CSR: decoupled-lookback scan ----------------
__global__ void __launch_bounds__(SCAN_B) k_scan_lb(
    const int* __restrict__ deg, int* __restrict__ off_u, int* __restrict__ off_r,
    int n, int etot) {
    __shared__ int sh[SCAN_B];
    __shared__ int s_prefix;
    int b = blockIdx.x;
    int i = b * SCAN_B + threadIdx.x;
    int v = (i < n) ? deg[i] : 0;
    sh[threadIdx.x] = v;
    __syncthreads();
    for (int s = 1; s < SCAN_B; s <<= 1) {
        int t = (threadIdx.x >= s) ? sh[threadIdx.x - s] : 0;
        __syncthreads();
        sh[threadIdx.x] += t;
        __syncthreads();
    }
    int incl_local = sh[threadIdx.x];
    int total = sh[SCAN_B - 1];
    if (threadIdx.x == 0) {
        if (b == 0) {
            atomicExch((ull*)&g_scan_state[0], ((ull)2 << 32) | (unsigned)total);
            s_prefix = 0;
        } else {
            atomicExch((ull*)&g_scan_state[b], ((ull)1 << 32) | (unsigned)total);
            int prefix = 0;
            for (int p = b - 1; p >= 0;) {
                ull st;
                do { st = g_scan_state[p]; } while ((st >> 32) == 0);
                prefix += (int)(unsigned)st;
                if ((st >> 32) == 2) break;
                p--;
            }
            atomicExch((ull*)&g_scan_state[b], ((ull)2 << 32) | (unsigned)(prefix + total));
            s_prefix = prefix;
        }
    }
    __syncthreads();
    int excl = s_prefix + incl_local - v;
    if (i < n) {
        if (i < NU) off_u[i] = excl;
        else        off_r[i - NU] = excl - etot;
        if (i == NU) off_u[NU] = excl;
        if (i == n - 1) off_r[NR] = excl + v - etot;
    }
}

__global__ void k_fill(const int* __restrict__ ei,
                       const int* __restrict__ off_u, const int* __restrict__ off_r,
                       int* __restrict__ cur,
                       int* __restrict__ nbr_u, int* __restrict__ nbr_r, int e) {
    int i = blockIdx.x * blockDim.x + threadIdx.x;
    if (i < e) {
        int s = ei[i], d = ei[e + i];
        int pu = atomicAdd(&cur[s], 1);
        nbr_u[off_u[s] + pu] = d;
        int pr = atomicAdd(&cur[NU + d], 1);
        nbr_r[off_r[d] + pr] = s;
    }
}

// ---------------- fp16 mean aggregation: warp per node, 8 lanes per neighbor row ----
// Pairwise HADD2 fold before fp32 conversion: 5 instr per word-pair vs 8.
__global__ void __launch_bounds__(256) k_aggregate_h(
    const int* __restrict__ off, const int* __restrict__ nbr,
    const __half* __restrict__ xsrc, float* __restrict__ mean, int n) {
    int w = (blockIdx.x * blockDim.x + threadIdx.x) >> 5;
    int lane = threadIdx.x & 31;
    if (w >= n) return;
    int beg = off[w], end = off[w + 1];
    int q = lane >> 3;       // neighbor slot 0..3
    int c = lane & 7;        // 16B chunk within 128B row
    const uint4* X = (const uint4*)xsrc;   // row = 8 uint4
    float a[8];
#pragma unroll
    for (int i = 0; i < 8; i++) a[i] = 0.f;

    for (int j = beg; j < end; j += 32) {
        int cnt = end - j; if (cnt > 32) cnt = 32;
        int idx = (lane < cnt) ? nbr[j + lane] : 0;
        int t = 0;
        for (; t + 8 <= cnt; t += 8) {
            int r0 = __shfl_sync(0xffffffffu, idx, t + q);
            int r1 = __shfl_sync(0xffffffffu, idx, t + 4 + q);
            uint4 v0 = X[(size_t)r0 * 8 + c];
            uint4 v1 = X[(size_t)r1 * 8 + c];
#pragma unroll
            for (int p = 0; p < 4; p++) {
                uint uw0 = (&v0.x)[p], uw1 = (&v1.x)[p];
                __half2 s = __hadd2(*(__half2*)&uw0, *(__half2*)&uw1);
                float2 f = __half22float2(s);
                a[2 * p]     += f.x;
                a[2 * p + 1] += f.y;
            }
        }
        for (; t < cnt; t += 4) {
            int u = t + q;
            int r = __shfl_sync(0xffffffffu, idx, (u < cnt) ? u : t);
            if (u < cnt) {
                uint4 v = X[(size_t)r * 8 + c];
#pragma unroll
                for (int p = 0; p < 4; p++) {
                    uint uw = (&v.x)[p];
                    float2 f = __half22float2(*(__half2*)&uw);
                    a[2 * p]     += f.x;
                    a[2 * p + 1] += f.y;
                }
            }
        }
    }
    // fold neighbor slots q=0..3 (lanes 0-7 end with totals)
#pragma unroll
    for (int i = 0; i < 8; i++) {
        a[i] += __shfl_down_sync(0xffffffffu, a[i], 16);
        a[i] += __shfl_down_sync(0xffffffffu, a[i], 8);
    }
    if (lane < 8) {
        float inv = 1.0f / fmaxf((float)(end - beg), 1.0f);
        float4* mp = (float4*)(mean + (size_t)w * 64 + c * 8);
        mp[0] = make_float4(a[0] * inv, a[1] * inv, a[2] * inv, a[3] * inv);
        mp[1] = make_float4(a[4] * inv, a[5] * inv, a[6] * inv, a[7] * inv);
    }
}

// ---------------- weight prep: Wt[n][k] bf16 hi/lo ----------------
__global__ void __launch_bounds__(128) k_prep_w(
    const float* __restrict__ Wl, const float* __restrict__ Wr) {
    const int offs[4] = {0, 4096, 12288, 8192};  // T0:r0 T1:u0 T2:u1 T3:r1
    int b = blockIdx.x;
    int off = offs[b];
    __nv_bfloat16* hi = (__nv_bfloat16*)g_bw[b];
    __nv_bfloat16* lo = hi + 8192;
    for (int i = threadIdx.x; i < 8192; i += 128) {
        int n = i >> 7, k = i & 127;
        float w = (k < 64) ? Wl[off + k * 64 + n] : Wr[off + (k - 64) * 64 + n];
        __nv_bfloat16 h = __float2bfloat16(w);
        hi[i] = h;
        lo[i] = __float2bfloat16(w - __bfloat162float(h));
    }
}

// ---------------- HMMA transform ----------------
#define KPAD 136
#define SA_WORDS (128 * (KPAD / 2))
#define SB_WORDS (64 * (KPAD / 2))
#define SM_AH 0
#define SM_AL (SA_WORDS)
#define SM_BH (2 * SA_WORDS)
#define SM_BL (2 * SA_WORDS + SB_WORDS)
#define SM_WORDS (2 * SA_WORDS + 2 * SB_WORDS)   // 104448 B

__global__ void __launch_bounds__(256) k_tmma(
    const float* __restrict__ A0, const float* __restrict__ A1,
    const unsigned char* __restrict__ bw,
    const float* __restrict__ bias, float* __restrict__ out,
    __half* __restrict__ out16, int n, int relu) {
    extern __shared__ uint smem[];
    uint* ah = smem + SM_AH;
    uint* al = smem + SM_AL;
    uint* bh = smem + SM_BH;
    uint* bl = smem + SM_BL;
    const int tid = threadIdx.x;
    const int rbase = blockIdx.x * 128;

    {
        const uint* bs = (const uint*)bw;
#pragma unroll
        for (int it = 0; it < 16; it++) {
            int u = tid + it * 256;
            int nn = u >> 6, kw = u & 63;
            int d = nn * (KPAD / 2) + kw;
            bh[d] = bs[u];
            bl[d] = bs[4096 + u];
        }
    }

#pragma unroll
    for (int it = 0; it < 16; it++) {
        int idx4 = tid + it * 256;
        int r = idx4 >> 5, qq = idx4 & 31;
        int gr = rbase + r; if (gr >= n) gr = rbase;
        const float4* sp = (const float4*)((qq < 16 ? A0 : A1) + (size_t)gr * 64) + (qq & 15);
        float4 v = *sp;
        uint h01, l01, h23, l23;
        split2(make_float2(v.x, v.y), h01, l01);
        split2(make_float2(v.z, v.w), h23, l23);
        int ui = r * (KPAD / 2) + qq * 2;
        ah[ui] = h01; ah[ui + 1] = h23;
        al[ui] = l01; al[ui + 1] = l23;
    }
    __syncthreads();

    const int wid = tid >> 5, lane = tid & 31;
    const int g = lane >> 2, tg = lane & 3;
    const int rowA = wid * 16 + g;
    const int rowA8 = rowA + 8;

    float acc[8][4];
#pragma unroll
    for (int j = 0; j < 8; j++)
#pragma unroll
        for (int q = 0; q < 4; q++) acc[j][q] = 0.f;

#pragma unroll
    for (int kk = 0; kk < 8; kk++) {
        int kw = kk * 8 + tg;
        uint ah0 = ah[rowA * (KPAD / 2) + kw];
        uint ah1 = ah[rowA8 * (KPAD / 2) + kw];
        uint ah2 = ah[rowA * (KPAD / 2) + kw + 4];
        uint ah3 = ah[rowA8 * (KPAD / 2) + kw + 4];
        uint al0 = al[rowA * (KPAD / 2) + kw];
        uint al1 = al[rowA8 * (KPAD / 2) + kw];
        uint al2 = al[rowA * (KPAD / 2) + kw + 4];
        uint al3 = al[rowA8 * (KPAD / 2) + kw + 4];
#pragma unroll
        for (int j = 0; j < 8; j++) {
            int nrow = j * 8 + g;
            uint bh0 = bh[nrow * (KPAD / 2) + kw];
            uint bh1 = bh[nrow * (KPAD / 2) + kw + 4];
            uint bl0 = bl[nrow * (KPAD / 2) + kw];
            uint bl1 = bl[nrow * (KPAD / 2) + kw + 4];
            mma16816(acc[j], ah0, ah1, ah2, ah3, bh0, bh1);
            mma16816(acc[j], al0, al1, al2, al3, bh0, bh1);
            mma16816(acc[j], ah0, ah1, ah2, ah3, bl0, bl1);
        }
    }

    int row1 = rbase + rowA;
    int row2 = row1 + 8;
#pragma unroll
    for (int j = 0; j < 8; j++) {
        int col = j * 8 + tg * 2;
        float2 bb = *(const float2*)(bias + col);
        float2 o1 = make_float2(acc[j][0] + bb.x, acc[j][1] + bb.y);
        float2 o2 = make_float2(acc[j][2] + bb.x, acc[j][3] + bb.y);
        if (relu) {
            o1.x = fmaxf(o1.x, 0.f); o1.y = fmaxf(o1.y, 0.f);
            o2.x = fmaxf(o2.x, 0.f); o2.y = fmaxf(o2.y, 0.f);
        }
        if (row1 < n) {
            *(float2*)(out + (size_t)row1 * 64 + col) = o1;
            if (out16) {
                __half2 p = __floats2half2_rn(o1.x, o1.y);
                *(__half2*)(out16 + (size_t)row1 * 64 + col) = p;
            }
        }
        if (row2 < n) {
            *(float2*)(out + (size_t)row2 * 64 + col) = o2;
            if (out16) {
                __half2 p = __floats2half2_rn(o2.x, o2.y);
                *(__half2*)(out16 + (size_t)row2 * 64 + col) = p;
            }
        }
    }
}

// ---------------- x_recipe init (writes fp32 + fp16) ----------------
__global__ void __launch_bounds__(256) k_init_recipe(
    const float* __restrict__ rx, const float* __restrict__ lw,
    const float* __restrict__ lb, const float* __restrict__ remb,
    float* __restrict__ xout, __half* __restrict__ xout16, int n) {
    __shared__ float slw[640];
    __shared__ float slb[64];
    int t = threadIdx.x;
    for (int i = t; i < 640; i += 256) slw[i] = lw[i];
    if (t < 64) slb[t] = lb[t];
    __syncthreads();
    int idx4 = blockIdx.x * 256 + t;
    if (idx4 >= n * 16) return;
    int r = idx4 >> 4;
    int h0 = (idx4 & 15) * 4;
    float4 acc = make_float4(slb[h0], slb[h0 + 1], slb[h0 + 2], slb[h0 + 3]);
    const float* xr = rx + r * 10;
#pragma unroll
    for (int k = 0; k < 10; k++) {
        float xv = xr[k];
        const float* wr = slw + k * 64 + h0;
        acc.x = fmaf(xv, wr[0], acc.x);
        acc.y = fmaf(xv, wr[1], acc.y);
        acc.z = fmaf(xv, wr[2], acc.z);
        acc.w = fmaf(xv, wr[3], acc.w);
    }
    float4 e = ((const float4*)remb)[idx4];
    acc.x += e.x; acc.y += e.y; acc.z += e.z; acc.w += e.w;
    ((float4*)xout)[idx4] = acc;
    __half2 ha = __floats2half2_rn(acc.x, acc.y);
    __half2 hb = __floats2half2_rn(acc.z, acc.w);
    ((uint2*)xout16)[idx4] = make_uint2(*(uint*)&ha, *(uint*)&hb);
}

// ---------------- classifier: half-warp per label edge (fp32 finals) ----------------
__global__ void __launch_bounds__(256) k_classify(
    const int* __restrict__ eli, const float* __restrict__ xu,
    const float* __restrict__ xr, float* __restrict__ out, int nl) {
    int hw = (blockIdx.x * blockDim.x + threadIdx.x) >> 4;
    int hl = threadIdx.x & 15;
    if (hw >= nl) return;
    int a = eli[hw], b = eli[nl + hw];
    float4 va = ((const float4*)xu)[(size_t)a * 16 + hl];
    float4 vb = ((const float4*)xr)[(size_t)b * 16 + hl];
    float s = va.x * vb.x + va.y * vb.y + va.z * vb.z + va.w * vb.w;
    s += __shfl_down_sync(0xffffffffu, s, 8, 16);
    s += __shfl_down_sync(0xffffffffu, s, 4, 16);
    s += __shfl_down_sync(0xffffffffu, s, 2, 16);
    s += __shfl_down_sync(0xffffffffu, s, 1, 16);
    if (hl == 0) out[hw] = s;
}

// ---------------- launch ----------------
extern "C" void kernel_launch(void* const* d_in, const int* in_sizes, int n_in,
                              void* d_out, int out_size) {
    const float* recipe_x   = (const float*)d_in[2];
    const int*   edge_index = (const int*)d_in[3];
    const int*   eli        = (const int*)d_in[4];
    const float* user_emb   = (const float*)d_in[5];
    const float* recipe_emb = (const float*)d_in[6];
    const float* lin_w      = (const float*)d_in[7];
    const float* lin_b      = (const float*)d_in[8];
    const float* Wl         = (const float*)d_in[9];
    const float* bl         = (const float*)d_in[10];
    const float* Wr         = (const float*)d_in[11];
    float* out = (float*)d_out;
    int E_ = in_sizes[3] / 2;
    int L_ = in_sizes[4] / 2;

    float *xr0, *xr1, *xu1, *xu2, *mean_r, *mean_u, *mean_r2, *mean_u2;
    __half *uh16, *xr0h, *xr1h, *xu1h;
    int *nbr_r, *nbr_u, *off_u, *off_r, *deg, *cur;
    unsigned char* bw;
    cudaGetSymbolAddress((void**)&xr0,     g_xr0);
    cudaGetSymbolAddress((void**)&xr1,     g_xr1);
    cudaGetSymbolAddress((void**)&xu1,     g_xu1);
    cudaGetSymbolAddress((void**)&xu2,     g_xu2);
    cudaGetSymbolAddress((void**)&mean_r,  g_mean_r);
    cudaGetSymbolAddress((void**)&mean_u,  g_mean_u);
    cudaGetSymbolAddress((void**)&mean_r2, g_mean_r2);
    cudaGetSymbolAddress((void**)&mean_u2, g_mean_u2);
    cudaGetSymbolAddress((void**)&uh16,    g_uh16);
    cudaGetSymbolAddress((void**)&xr0h,    g_xr0h);
    cudaGetSymbolAddress((void**)&xr1h,    g_xr1h);
    cudaGetSymbolAddress((void**)&xu1h,    g_xu1h);
    cudaGetSymbolAddress((void**)&nbr_r,   g_nbr_r);
    cudaGetSymbolAddress((void**)&nbr_u,   g_nbr_u);
    cudaGetSymbolAddress((void**)&off_u,   g_off_u);
    cudaGetSymbolAddress((void**)&off_r,   g_off_r);
    cudaGetSymbolAddress((void**)&deg,     g_deg);
    cudaGetSymbolAddress((void**)&cur,     g_cur);
    cudaGetSymbolAddress((void**)&bw,      g_bw);

    const int TM_SMEM = SM_WORDS * 4;
    cudaFuncSetAttribute(k_tmma, cudaFuncAttributeMaxDynamicSharedMemorySize, TM_SMEM);

    const int TMB  = (NU + 127) / 128;
    const int AGGB = (NR * 32 + 255) / 256;

    cudaMemsetAsync(deg, 0, M2 * sizeof(int), 0);
    cudaMemsetAsync(cur, 0, M2 * sizeof(int), 0);

    // CSR build (+ user_emb fp16 mirror inside k_count)
    k_count  <<<(E_ + 255) / 256, 256>>>(edge_index, deg, user_emb, E_);   // #1
    k_scan_lb<<<NSCANB, SCAN_B>>>(deg, off_u, off_r, M2, E_);              // #2
    k_fill   <<<(E_ + 255) / 256, 256>>>(edge_index, off_u, off_r, cur,
                                         nbr_u, nbr_r, E_);                // #3

    // #4: agg_r0 (fp16 gather, profiled)
    k_aggregate_h<<<AGGB, 256>>>(off_r, nbr_r, uh16, mean_r, NR);

    // #5: weight prep; #6: x_recipe init (fp32 + fp16)
    k_prep_w<<<4, 128>>>(Wl, Wr);
    k_init_recipe<<<(NR * 16 + 255) / 256, 256>>>(recipe_x, lin_w, lin_b,
                                                  recipe_emb, xr0, xr0h, NR);

    // #7: agg_u0
    k_aggregate_h<<<AGGB, 256>>>(off_u, nbr_u, xr0h, mean_u, NU);

    // #8-9: layer-0 transforms (relu, dual-store fp16)
    k_tmma<<<TMB, 256, TM_SMEM>>>(mean_r, xr0, bw + 0 * 32768, bl,      xr1, xr1h, NR, 1);
    k_tmma<<<TMB, 256, TM_SMEM>>>(mean_u, user_emb, bw + 1 * 32768, bl + 64, xu1, xu1h, NU, 1);

    // #10-11: layer-1 aggregations (fp16 gather)
    k_aggregate_h<<<AGGB, 256>>>(off_u, nbr_u, xr1h, mean_u2, NU);
    k_aggregate_h<<<AGGB, 256>>>(off_r, nbr_r, xu1h, mean_r2, NR);

    // #12-13: layer-1 transforms (fp32 only)
    k_tmma<<<TMB, 256, TM_SMEM>>>(mean_u2, xu1, bw + 2 * 32768, bl + 192, xu2, (__half*)0, NU, 0);
    k_tmma<<<TMB, 256, TM_SMEM>>>(mean_r2, xr1, bw + 3 * 32768, bl + 128, xr0, (__half*)0, NR, 0);

    // #14: classifier
    k_classify<<<(L_ * 16 + 255) / 256, 256>>>(eli, xu2, xr0, out, L_);
}